// round 15
// baseline (speedup 1.0000x reference)
#include <cuda_runtime.h>
#include <cuda_fp16.h>
#include <math.h>

#define DIMV   64
#define NEMB   512
#define TPB    512
#define TILE_M 128
#define ROWB   144          // padded row stride: 72 fp16 (conflict-free ldmatrix)
#define POS_OFF 192.0f      // positivity offset folded into screen init

// ---------------- smem layout (bytes) ----------------
#define B_HI_OFF   0                          // 512 x 144B fp16 (-2w hi)
#define B_LO_OFF   (512*ROWB)                 // 73728
#define A_HI_OFF   (2*512*ROWB)               // 147456, 128 x 144B
#define A_LO_OFF   (A_HI_OFF + 128*ROWB)      // 165888
#define STAGE_OFF  (A_LO_OFF + 128*ROWB)      // 184320, raw fp32 tile 32KB
#define SWSQ_OFF   (STAGE_OFF + 32768)        // 217088, 512 f32 (exact, refine)
#define SCNT_OFF   (SWSQ_OFF + 2048)          // 512 f32
#define SWSQP_OFF  (SCNT_OFF + 2048)          // 512 f32 (wsq + POS_OFF, screen)
#define SKEY_OFF   (SWSQP_OFF + 2048)         // 2 x 128 x 2 u32 = 2048
#define SJ_OFF     (SKEY_OFF + 2048)          // 128 i32
#define SLOSS_OFF  (SJ_OFF + 512)
#define SMEM_BYTES (SLOSS_OFF + 16)           // 225808

// ---------------- device scratch ----------------
__device__ __align__(16) float g_embed_sum[NEMB * DIMV];  // code-major [j][k]
__device__ float g_counts[NEMB];
__device__ float g_loss_sum;

// ---------------- helpers ----------------
__device__ __forceinline__ unsigned smem_u32(const void* p) {
    unsigned a;
    asm("{ .reg .u64 t; cvta.to.shared.u64 t, %1; cvt.u32.u64 %0, t; }" : "=r"(a) : "l"(p));
    return a;
}
__device__ __forceinline__ unsigned ford(float f) {
    unsigned u = __float_as_uint(f);
    unsigned m = (unsigned)((int)u >> 31) | 0x80000000u;
    return u ^ m;
}
__device__ __forceinline__ unsigned long long packkey(float v, int j) {
    return ((unsigned long long)ford(v) << 32) | (unsigned)j;
}
__device__ __forceinline__ unsigned umn(unsigned a, unsigned b) { return a < b ? a : b; }
__device__ __forceinline__ unsigned umx(unsigned a, unsigned b) { return a > b ? a : b; }
__device__ __forceinline__ unsigned long long u64min(unsigned long long a, unsigned long long b) {
    return a < b ? a : b;
}
__device__ __forceinline__ unsigned long long u64max(unsigned long long a, unsigned long long b) {
    return a > b ? a : b;
}
// expand 8-bit-index half key to u64 with full 9-bit code index
__device__ __forceinline__ unsigned long long kexp(unsigned k, unsigned half) {
    return ((unsigned long long)(k & 0xFFFFFF00u) << 8)
         | (unsigned)((half << 8) | (k & 0xFFu));
}
__device__ __forceinline__ void ldm_x4(unsigned &r0, unsigned &r1, unsigned &r2, unsigned &r3,
                                       unsigned addr) {
    asm volatile("ldmatrix.sync.aligned.m8n8.x4.shared.b16 {%0,%1,%2,%3}, [%4];"
                 : "=r"(r0), "=r"(r1), "=r"(r2), "=r"(r3) : "r"(addr));
}
__device__ __forceinline__ void mma_fp16(float* d, const unsigned* a, unsigned b0, unsigned b1) {
    asm volatile("mma.sync.aligned.m16n8k16.row.col.f32.f16.f16.f32 "
                 "{%0,%1,%2,%3},{%4,%5,%6,%7},{%8,%9},{%0,%1,%2,%3};"
                 : "+f"(d[0]), "+f"(d[1]), "+f"(d[2]), "+f"(d[3])
                 : "r"(a[0]), "r"(a[1]), "r"(a[2]), "r"(a[3]), "r"(b0), "r"(b1));
}
__device__ __forceinline__ void red_add_v4(float* p, float a, float b, float c, float d) {
    asm volatile("red.global.add.v4.f32 [%0], {%1,%2,%3,%4};"
                 :: "l"(p), "f"(a), "f"(b), "f"(c), "f"(d) : "memory");
}
__device__ __forceinline__ void cp_async16(unsigned dst, const void* src) {
    asm volatile("cp.async.cg.shared.global [%0], [%1], 16;" :: "r"(dst), "l"(src) : "memory");
}
#define CP_COMMIT() asm volatile("cp.async.commit_group;" ::: "memory")
#define CP_WAIT0()  asm volatile("cp.async.wait_group 0;" ::: "memory")
__device__ __forceinline__ float2 h2f2(unsigned u) {
    __half2 h = *(__half2*)&u;
    return __half22float2(h);
}
__device__ __forceinline__ void cvt_hl(float v, unsigned &h, unsigned &l) {
    float m = -2.0f * v;
    __half hh = __float2half_rn(m);
    __half ll = __float2half_rn(m - __half2float(hh));
    h = (unsigned)__half_as_ushort(hh);
    l = (unsigned)__half_as_ushort(ll);
}

// ---------------------------------------------------------------------------
// Kernel: persistent main — per-block codebook convert + fp16 HMMA screen
//         (8-bit-idx positive keys) + exact top-2 refine
// ---------------------------------------------------------------------------
__global__ __launch_bounds__(TPB, 1)
void vq_main(const float* __restrict__ inp, const float* __restrict__ w, int nrows) {
    extern __shared__ __align__(1024) char sm[];
    const unsigned sbase = smem_u32(sm);
    const int tid  = threadIdx.x;
    const int lane = tid & 31;
    const int wid  = tid >> 5;
    const int mgrp = wid >> 1;      // 0..7 : row group of 16
    const int nh   = wid & 1;       // 0..1 : code half of 256

    float* swsq  = (float*)(sm + SWSQ_OFF);
    float* scnt  = (float*)(sm + SCNT_OFF);
    float* swsqp = (float*)(sm + SWSQP_OFF);
    unsigned* skey = (unsigned*)(sm + SKEY_OFF);
    int*   sj    = (int*)(sm + SJ_OFF);
    float* sloss = (float*)(sm + SLOSS_OFF);

    // --- per-block codebook convert: w column j -> B_HI/B_LO row j + swsq ---
    {
        const int j = tid;
        char* rowH = sm + B_HI_OFF + j * ROWB;
        char* rowL = sm + B_LO_OFF + j * ROWB;
        float s = 0.0f;
#pragma unroll
        for (int k = 0; k < DIMV; k += 4) {
            float v0 = w[(k + 0) * NEMB + j];
            float v1 = w[(k + 1) * NEMB + j];
            float v2 = w[(k + 2) * NEMB + j];
            float v3 = w[(k + 3) * NEMB + j];
            s = fmaf(v0, v0, fmaf(v1, v1, fmaf(v2, v2, fmaf(v3, v3, s))));
            unsigned h0, l0, h1, l1, h2, l2, h3, l3;
            cvt_hl(v0, h0, l0); cvt_hl(v1, h1, l1);
            cvt_hl(v2, h2, l2); cvt_hl(v3, h3, l3);
            unsigned long long hw = ((unsigned long long)(h2 | (h3 << 16)) << 32) | (h0 | (h1 << 16));
            unsigned long long lw = ((unsigned long long)(l2 | (l3 << 16)) << 32) | (l0 | (l1 << 16));
            *(unsigned long long*)(rowH + k * 2) = hw;
            *(unsigned long long*)(rowL + k * 2) = lw;
        }
        swsq[j]  = s;
        swsqp[j] = s + POS_OFF;
        scnt[j]  = 0.0f;
        if (tid == 0) *sloss = 0.0f;
    }

    // lane-fixed ldmatrix address offsets
    const unsigned aoff = (unsigned)((lane & 15) * ROWB + (lane >> 4) * 16);
    const unsigned boff = (unsigned)(((lane & 7) + ((lane >> 4) << 3)) * ROWB + ((lane >> 3) & 1) * 16);
    const unsigned aHbase = sbase + A_HI_OFF + (unsigned)(mgrp * 16 * ROWB) + aoff;
    const unsigned bHbase = sbase + B_HI_OFF + (unsigned)(nh * 256 * ROWB) + boff;

    float loss_acc = 0.0f;
    const int nchunks = nrows / TILE_M;

    // ---- prefetch first tile into staging ----
    {
        const float4* src = (const float4*)inp + (size_t)blockIdx.x * (TILE_M * DIMV / 4);
#pragma unroll
        for (int i = 0; i < 4; i++)
            cp_async16(sbase + STAGE_OFF + (tid + i * TPB) * 16, src + tid + i * TPB);
        CP_COMMIT();
    }
    __syncthreads();   // B smem + swsq/swsqp visible to all warps

    for (int tile = blockIdx.x; tile < nchunks; tile += gridDim.x) {
        CP_WAIT0();
        __syncthreads();   // S1: staging visible; prev refine/scatter done

        // ---- convert x -> fp16 hi/lo in smem (x kept in v regs) ----
        float4 v[4];
        const float4* stg = (const float4*)(sm + STAGE_OFF);
#pragma unroll
        for (int i = 0; i < 4; i++) {
            int idx = tid + i * TPB;
            float4 x = stg[idx];
            v[i] = x;
            __half h0 = __float2half_rn(x.x), h1 = __float2half_rn(x.y);
            __half h2 = __float2half_rn(x.z), h3 = __float2half_rn(x.w);
            __half l0 = __float2half_rn(x.x - __half2float(h0));
            __half l1 = __float2half_rn(x.y - __half2float(h1));
            __half l2 = __float2half_rn(x.z - __half2float(h2));
            __half l3 = __float2half_rn(x.w - __half2float(h3));
            unsigned hw0 = __half_as_ushort(h0) | ((unsigned)__half_as_ushort(h1) << 16);
            unsigned hw1 = __half_as_ushort(h2) | ((unsigned)__half_as_ushort(h3) << 16);
            unsigned lw0 = __half_as_ushort(l0) | ((unsigned)__half_as_ushort(l1) << 16);
            unsigned lw1 = __half_as_ushort(l2) | ((unsigned)__half_as_ushort(l3) << 16);
            unsigned long long hw = ((unsigned long long)hw1 << 32) | hw0;
            unsigned long long lw = ((unsigned long long)lw1 << 32) | lw0;
            int row = idx >> 4, kc = idx & 15;
            *(unsigned long long*)(sm + A_HI_OFF + row * ROWB + kc * 8) = hw;
            *(unsigned long long*)(sm + A_LO_OFF + row * ROWB + kc * 8) = lw;
        }
        __syncthreads();   // S2: A smem ready; staging reads done

        // ---- prefetch next tile (overlaps MMA) ----
        {
            int nxt = tile + gridDim.x;
            if (nxt < nchunks) {
                const float4* src = (const float4*)inp + (size_t)nxt * (TILE_M * DIMV / 4);
#pragma unroll
                for (int i = 0; i < 4; i++)
                    cp_async16(sbase + STAGE_OFF + (tid + i * TPB) * 16, src + tid + i * TPB);
            }
            CP_COMMIT();
        }

        // ---- load A hi fragments ----
        unsigned Ah[4][4];
#pragma unroll
        for (int ks = 0; ks < 4; ks++)
            ldm_x4(Ah[ks][0], Ah[ks][1], Ah[ks][2], Ah[ks][3], aHbase + (unsigned)(ks * 32));

        // ---- single-pass screen GEMM; 8-bit-index positive-key top-2 ----
        unsigned bk1[2] = {0xFFFFFFFFu, 0xFFFFFFFFu};
        unsigned bk2[2] = {0xFFFFFFFFu, 0xFFFFFFFFu};

#pragma unroll
        for (int chunk = 0; chunk < 4; chunk++) {
            float acc[8][4];
            int jb0 = chunk * 64 + (lane & 3) * 2;      // local index within half
#pragma unroll
            for (int nt = 0; nt < 8; nt++) {
                float2 wq = *(float2*)(swsqp + nh * 256 + jb0 + nt * 8);
                acc[nt][0] = wq.x; acc[nt][1] = wq.y;
                acc[nt][2] = wq.x; acc[nt][3] = wq.y;
            }
            unsigned bc = (unsigned)(chunk * 64 * ROWB);
#pragma unroll
            for (int ks = 0; ks < 4; ks++) {
                unsigned B0[4][4];
#pragma unroll
                for (int pr = 0; pr < 4; pr++) {
                    unsigned off = bc + (unsigned)(pr * 16 * ROWB + ks * 32);
                    ldm_x4(B0[pr][0], B0[pr][1], B0[pr][2], B0[pr][3], bHbase + off);
                }
#pragma unroll
                for (int pr = 0; pr < 4; pr++) {
                    mma_fp16(acc[2*pr],   Ah[ks], B0[pr][0], B0[pr][1]);
                    mma_fp16(acc[2*pr+1], Ah[ks], B0[pr][2], B0[pr][3]);
                }
            }
            // fold: values = d + POS_OFF > 0; key = (bits & ~0xFF) | j8
#pragma unroll
            for (int nt = 0; nt < 8; nt++) {
                int jb = jb0 + nt * 8;
#pragma unroll
                for (int q = 0; q < 4; q++) {
                    int s = q >> 1;
                    unsigned key = (__float_as_uint(acc[nt][q]) & ~0xFFu) | (unsigned)(jb + (q & 1));
                    unsigned t = umx(bk1[s], key);
                    bk1[s] = umn(bk1[s], key);
                    bk2[s] = umn(bk2[s], t);
                }
            }
        }

        // ---- quad-merge u32 top-2, owners write per-half keys ----
#pragma unroll
        for (int s = 0; s < 2; s++) {
            unsigned k1 = bk1[s], k2 = bk2[s];
#pragma unroll
            for (int off = 1; off <= 2; off <<= 1) {
                unsigned o1 = __shfl_xor_sync(0xFFFFFFFFu, k1, off);
                unsigned o2 = __shfl_xor_sync(0xFFFFFFFFu, k2, off);
                unsigned t = umx(k1, o1);
                k1 = umn(k1, o1);
                k2 = umn(k2, umn(o2, t));
            }
            if ((lane & 3) == 0) {
                int r = mgrp * 16 + (lane >> 2) + s * 8;
                skey[(nh * 128 + r) * 2]     = k1;
                skey[(nh * 128 + r) * 2 + 1] = k2;
            }
        }
        __syncthreads();   // S3: both halves' top-2 keys in smem

        // ---- exact refine: expand half-keys to 9-bit j, merge, recompute ----
        if (tid < 2 * TILE_M) {
            int r = tid >> 1;
            unsigned long long ea1 = kexp(skey[r * 2], 0);
            unsigned long long ea2 = kexp(skey[r * 2 + 1], 0);
            unsigned long long eb1 = kexp(skey[(128 + r) * 2], 1);
            unsigned long long eb2 = kexp(skey[(128 + r) * 2 + 1], 1);
            unsigned long long m1 = u64min(ea1, eb1);
            unsigned long long m2 = u64min(u64max(ea1, eb1), u64min(ea2, eb2));
            int j = (int)(((tid & 1) ? m2 : m1) & 0x1FFull);

            const uint4* xh4 = (const uint4*)(sm + A_HI_OFF + r * ROWB);
            const uint4* xl4 = (const uint4*)(sm + A_LO_OFF + r * ROWB);
            const uint4* wh4 = (const uint4*)(sm + B_HI_OFF + j * ROWB);
            const uint4* wl4 = (const uint4*)(sm + B_LO_OFF + j * ROWB);
            float d  = swsq[j], d2 = 0.0f;
            float e  = 0.0f,    e2 = 0.0f;        // ||x||^2 split chains
#pragma unroll
            for (int c = 0; c < 8; c++) {
                uint4 hx = xh4[c], lx = xl4[c], hw = wh4[c], lw = wl4[c];
                const unsigned hxs[4] = {hx.x, hx.y, hx.z, hx.w};
                const unsigned lxs[4] = {lx.x, lx.y, lx.z, lx.w};
                const unsigned hws[4] = {hw.x, hw.y, hw.z, hw.w};
                const unsigned lws[4] = {lw.x, lw.y, lw.z, lw.w};
#pragma unroll
                for (int u = 0; u < 4; u++) {
                    float2 xa = h2f2(hxs[u]), xb = h2f2(lxs[u]);
                    float2 wa = h2f2(hws[u]), wb = h2f2(lws[u]);
                    float xx0 = xa.x + xb.x, xx1 = xa.y + xb.y;
                    float ww0 = wa.x + wb.x, ww1 = wa.y + wb.y;
                    d  = fmaf(xx0, ww0, d);
                    d2 = fmaf(xx1, ww1, d2);
                    e  = fmaf(xx0, xx0, e);
                    e2 = fmaf(xx1, xx1, e2);
                }
            }
            d += d2;
            e += e2;
            unsigned long long kd = packkey(d, j);
            unsigned long long ko = __shfl_xor_sync(0xFFFFFFFFu, kd, 1);
            if ((tid & 1) == 0) {
                unsigned long long kw = u64min(kd, ko);
                int jw = (int)(kw & 0xFFFFFFFFull);
                float dw;
                { unsigned m = (unsigned)(kw >> 32);
                  unsigned uu = (m & 0x80000000u) ? (m ^ 0x80000000u) : ~m;
                  dw = __uint_as_float(uu); }
                sj[r] = jw;
                loss_acc += dw + e;
                atomicAdd(&scnt[jw], 1.0f);
            }
        }
        __syncthreads();   // S4: sj ready

        // ---- embed_sum scatter straight from fp32 registers ----
#pragma unroll
        for (int i = 0; i < 4; i++) {
            int idx = tid + i * TPB;
            int r = idx >> 4;
            int j = sj[r];
            red_add_v4(g_embed_sum + j * DIMV + (idx & 15) * 4, v[i].x, v[i].y, v[i].z, v[i].w);
        }
    }

    // ---- flush block-local accumulators ----
    atomicAdd(sloss, loss_acc);
    __syncthreads();
    if (scnt[tid] != 0.0f) atomicAdd(&g_counts[tid], scnt[tid]);
    if (tid == 0) atomicAdd(&g_loss_sum, *sloss);
}

// ---------------------------------------------------------------------------
// Kernel (fused tail): every block redundantly reduces n, computes its 256
// outputs; block 0 additionally writes loss/perplexity/new_cluster_size.
// grid = 128 x 256: block b covers gid = b*256+t, k = b>>1, j = (b&1)*256 + t.
// ---------------------------------------------------------------------------
__global__ void vq_final(const float* __restrict__ cs_in,
                         const float* __restrict__ ea_in,
                         float* __restrict__ out, int nrows) {
    __shared__ float red[256];
    const int t = threadIdx.x;
    const int b = blockIdx.x;

    float c0 = g_counts[t], c1 = g_counts[t + 256];
    float ncs0 = fmaf(0.99f, cs_in[t], 0.01f * c0);
    float ncs1 = fmaf(0.99f, cs_in[t + 256], 0.01f * c1);

    red[t] = ncs0 + ncs1;
    __syncthreads();
#pragma unroll
    for (int off = 128; off; off >>= 1) {
        if (t < off) red[t] += red[t + off];
        __syncthreads();
    }
    float n = red[0];

    int gid = b * 256 + t;
    int k = gid >> 9;
    int j = (b & 1) * 256 + t;
    float ncs = (b & 1) ? ncs1 : ncs0;
    float csj = (ncs + 1e-5f) / (n + (float)NEMB * 1e-5f) * n;

    float ea = fmaf(0.99f, ea_in[gid], 0.01f * g_embed_sum[j * DIMV + k]);
    const int EA_OFF = 2 + DIMV * NEMB + NEMB;
    out[EA_OFF + gid] = ea;              // new_embed_avg
    out[2 + gid] = ea / csj;             // new_w

    if (b == 0) {
        out[2 + DIMV * NEMB + t]       = ncs0;   // new_cluster_size
        out[2 + DIMV * NEMB + t + 256] = ncs1;
        __syncthreads();
        float p0 = c0 / (float)nrows, p1 = c1 / (float)nrows;
        red[t] = fmaf(p0, logf(p0 + 1e-10f), p1 * logf(p1 + 1e-10f));
        __syncthreads();
#pragma unroll
        for (int off = 128; off; off >>= 1) {
            if (t < off) red[t] += red[t + off];
            __syncthreads();
        }
        if (t == 0) {
            out[1] = expf(-red[0]);
            out[0] = 0.25f * g_loss_sum / ((float)nrows * (float)DIMV);
        }
    }
}

// ---------------------------------------------------------------------------
extern "C" void kernel_launch(void* const* d_in, const int* in_sizes, int n_in,
                              void* d_out, int out_size) {
    const float* inp = (const float*)d_in[0];
    const float* w   = (const float*)d_in[1];
    const float* cs  = (const float*)d_in[2];
    const float* ea  = (const float*)d_in[3];
    int nrows = in_sizes[0] / DIMV;

    cudaFuncSetAttribute(vq_main, cudaFuncAttributeMaxDynamicSharedMemorySize, SMEM_BYTES);

    // zero scratch via memset nodes (graph-capturable, replaces vq_init)
    void *p_es, *p_cnt, *p_loss;
    cudaGetSymbolAddress(&p_es, g_embed_sum);
    cudaGetSymbolAddress(&p_cnt, g_counts);
    cudaGetSymbolAddress(&p_loss, g_loss_sum);
    cudaMemsetAsync(p_es, 0, NEMB * DIMV * sizeof(float));
    cudaMemsetAsync(p_cnt, 0, NEMB * sizeof(float));
    cudaMemsetAsync(p_loss, 0, sizeof(float));

    vq_main<<<148, TPB, SMEM_BYTES>>>(inp, w, nrows);
    vq_final<<<DIMV * NEMB / 256, 256>>>(cs, ea, (float*)d_out, nrows);
}

// round 16
// speedup vs baseline: 1.0841x; 1.0841x over previous
#include <cuda_runtime.h>
#include <cuda_fp16.h>
#include <math.h>

#define DIMV   64
#define NEMB   512
#define TPB    512
#define TILE_M 128
#define ROWB   144          // padded row stride: 72 fp16 (conflict-free ldmatrix)
#define POS_OFF 192.0f      // positivity offset folded into screen init

// ---------------- smem layout (bytes) ----------------
#define B_HI_OFF   0                          // 512 x 144B fp16 (-2w hi)
#define B_LO_OFF   (512*ROWB)                 // 73728
#define A_HI_OFF   (2*512*ROWB)               // 147456, 128 x 144B
#define A_LO_OFF   (A_HI_OFF + 128*ROWB)      // 165888
#define STAGE_OFF  (A_LO_OFF + 128*ROWB)      // 184320, raw fp32 tile 32KB
#define SWSQ_OFF   (STAGE_OFF + 32768)        // 217088, 512 f32 (exact, refine)
#define SCNT_OFF   (SWSQ_OFF + 2048)          // 512 f32
#define SWSQP_OFF  (SCNT_OFF + 2048)          // 512 f32 (wsq + POS_OFF, screen)
#define SKEY_OFF   (SWSQP_OFF + 2048)         // 2 x 128 x 2 u32 = 2048
#define SJ_OFF     (SKEY_OFF + 2048)          // 128 i32
#define SLOSS_OFF  (SJ_OFF + 512)
#define SMEM_BYTES (SLOSS_OFF + 16)           // 225808

// ---------------- device scratch ----------------
__device__ float          g_wsq[NEMB];
__device__ unsigned short g_w_hi[NEMB * DIMV];   // [j][k], -2w fp16 hi
__device__ unsigned short g_w_lo[NEMB * DIMV];   // fp16 residual
__device__ __align__(16) float g_embed_sum[NEMB * DIMV];  // code-major [j][k]
__device__ float          g_counts[NEMB];
__device__ float          g_loss_sum;

// ---------------- helpers ----------------
__device__ __forceinline__ unsigned smem_u32(const void* p) {
    unsigned a;
    asm("{ .reg .u64 t; cvta.to.shared.u64 t, %1; cvt.u32.u64 %0, t; }" : "=r"(a) : "l"(p));
    return a;
}
__device__ __forceinline__ unsigned ford(float f) {
    unsigned u = __float_as_uint(f);
    unsigned m = (unsigned)((int)u >> 31) | 0x80000000u;
    return u ^ m;
}
__device__ __forceinline__ unsigned long long packkey(float v, int j) {
    return ((unsigned long long)ford(v) << 32) | (unsigned)j;
}
__device__ __forceinline__ unsigned umn(unsigned a, unsigned b) { return a < b ? a : b; }
__device__ __forceinline__ unsigned umx(unsigned a, unsigned b) { return a > b ? a : b; }
__device__ __forceinline__ unsigned long long u64min(unsigned long long a, unsigned long long b) {
    return a < b ? a : b;
}
__device__ __forceinline__ unsigned long long u64max(unsigned long long a, unsigned long long b) {
    return a > b ? a : b;
}
// expand 8-bit-index half key to u64 with full 9-bit code index
__device__ __forceinline__ unsigned long long kexp(unsigned k, unsigned half) {
    return ((unsigned long long)(k & 0xFFFFFF00u) << 8)
         | (unsigned)((half << 8) | (k & 0xFFu));
}
__device__ __forceinline__ void ldm_x4(unsigned &r0, unsigned &r1, unsigned &r2, unsigned &r3,
                                       unsigned addr) {
    asm volatile("ldmatrix.sync.aligned.m8n8.x4.shared.b16 {%0,%1,%2,%3}, [%4];"
                 : "=r"(r0), "=r"(r1), "=r"(r2), "=r"(r3) : "r"(addr));
}
__device__ __forceinline__ void mma_fp16(float* d, const unsigned* a, unsigned b0, unsigned b1) {
    asm volatile("mma.sync.aligned.m16n8k16.row.col.f32.f16.f16.f32 "
                 "{%0,%1,%2,%3},{%4,%5,%6,%7},{%8,%9},{%0,%1,%2,%3};"
                 : "+f"(d[0]), "+f"(d[1]), "+f"(d[2]), "+f"(d[3])
                 : "r"(a[0]), "r"(a[1]), "r"(a[2]), "r"(a[3]), "r"(b0), "r"(b1));
}
__device__ __forceinline__ void red_add_v4(float* p, float a, float b, float c, float d) {
    asm volatile("red.global.add.v4.f32 [%0], {%1,%2,%3,%4};"
                 :: "l"(p), "f"(a), "f"(b), "f"(c), "f"(d) : "memory");
}
__device__ __forceinline__ void cp_async16(unsigned dst, const void* src) {
    asm volatile("cp.async.cg.shared.global [%0], [%1], 16;" :: "r"(dst), "l"(src) : "memory");
}
#define CP_COMMIT() asm volatile("cp.async.commit_group;" ::: "memory")
#define CP_WAIT0()  asm volatile("cp.async.wait_group 0;" ::: "memory")
__device__ __forceinline__ float2 h2f2(unsigned u) {
    __half2 h = *(__half2*)&u;
    return __half22float2(h);
}

// ---------------------------------------------------------------------------
// Kernel 1: coalesced init via smem transpose, 16-way parallel codebook.
// Blocks 0-15: codebook (32 codes each). Blocks 16-79: zero embed_sum/counts.
// ---------------------------------------------------------------------------
__global__ void vq_init(const float* __restrict__ w) {
    const int b = blockIdx.x;
    const int tid = threadIdx.x;

    if (b >= 16) {
        int idx = (b - 16) * 256 + tid;      // 0..16383
        ((float2*)g_embed_sum)[idx] = make_float2(0.0f, 0.0f);
        if (idx < NEMB) g_counts[idx] = 0.0f;
        if (b == 16 && tid == 0) g_loss_sum = 0.0f;
        return;
    }

    __shared__ float t[DIMV][33];            // transposed 64x32 tile, padded
    const int j0 = b * 32;
#pragma unroll
    for (int i = 0; i < 8; i++) {
        int idx = tid + i * 256;             // 0..2047
        int k = idx >> 5, jl = idx & 31;
        t[k][jl] = w[k * NEMB + j0 + jl];    // coalesced 128B per warp
    }
    __syncthreads();

    const int jl = tid >> 3;                 // 0..31
    const int kb = (tid & 7) * 8;            // 8 consecutive k per thread
    const int j  = j0 + jl;

    unsigned hi[4], lo[4];
    float s = 0.0f;
#pragma unroll
    for (int c = 0; c < 8; c += 2) {
        float v0 = t[kb + c][jl], v1 = t[kb + c + 1][jl];
        s = fmaf(v0, v0, fmaf(v1, v1, s));
        float m0 = -2.0f * v0, m1 = -2.0f * v1;
        __half h0 = __float2half_rn(m0), h1 = __float2half_rn(m1);
        __half l0 = __float2half_rn(m0 - __half2float(h0));
        __half l1 = __float2half_rn(m1 - __half2float(h1));
        hi[c >> 1] = __half_as_ushort(h0) | ((unsigned)__half_as_ushort(h1) << 16);
        lo[c >> 1] = __half_as_ushort(l0) | ((unsigned)__half_as_ushort(l1) << 16);
    }
    // contiguous 16B stores (8 threads cover one code row of 128B)
    *(uint4*)(g_w_hi + j * DIMV + kb) = make_uint4(hi[0], hi[1], hi[2], hi[3]);
    *(uint4*)(g_w_lo + j * DIMV + kb) = make_uint4(lo[0], lo[1], lo[2], lo[3]);

    // 8-thread reduce for ||w_j||^2
    s += __shfl_xor_sync(0xFFFFFFFFu, s, 1);
    s += __shfl_xor_sync(0xFFFFFFFFu, s, 2);
    s += __shfl_xor_sync(0xFFFFFFFFu, s, 4);
    if ((tid & 7) == 0) g_wsq[j] = s;
}

// ---------------------------------------------------------------------------
// Kernel 2: persistent main — fp16 HMMA screen (8-bit-idx keys) + exact refine
// ---------------------------------------------------------------------------
__global__ __launch_bounds__(TPB, 1)
void vq_main(const float* __restrict__ inp, int nrows) {
    extern __shared__ __align__(1024) char sm[];
    const unsigned sbase = smem_u32(sm);
    const int tid  = threadIdx.x;
    const int lane = tid & 31;
    const int wid  = tid >> 5;
    const int mgrp = wid >> 1;      // 0..7 : row group of 16
    const int nh   = wid & 1;       // 0..1 : code half of 256

    float* swsq  = (float*)(sm + SWSQ_OFF);
    float* scnt  = (float*)(sm + SCNT_OFF);
    float* swsqp = (float*)(sm + SWSQP_OFF);
    unsigned* skey = (unsigned*)(sm + SKEY_OFF);
    int*   sj    = (int*)(sm + SJ_OFF);
    float* sloss = (float*)(sm + SLOSS_OFF);

    // --- stage B (-2w hi/lo fp16) into padded rows + swsq(+offset) + counters ---
    {
        const uint4* srcH = (const uint4*)g_w_hi;
        const uint4* srcL = (const uint4*)g_w_lo;
#pragma unroll
        for (int i = 0; i < 8; i++) {
            int idx = tid + i * TPB;        // 0..4095 : 16B chunk index
            int row = idx >> 3, c = idx & 7;
            *(uint4*)(sm + B_HI_OFF + row * ROWB + c * 16) = srcH[idx];
            *(uint4*)(sm + B_LO_OFF + row * ROWB + c * 16) = srcL[idx];
        }
        float wq = g_wsq[tid];
        swsq[tid]  = wq;
        swsqp[tid] = wq + POS_OFF;
        scnt[tid]  = 0.0f;
        if (tid == 0) *sloss = 0.0f;
    }

    // lane-fixed ldmatrix address offsets
    const unsigned aoff = (unsigned)((lane & 15) * ROWB + (lane >> 4) * 16);
    const unsigned boff = (unsigned)(((lane & 7) + ((lane >> 4) << 3)) * ROWB + ((lane >> 3) & 1) * 16);
    const unsigned aHbase = sbase + A_HI_OFF + (unsigned)(mgrp * 16 * ROWB) + aoff;
    const unsigned bHbase = sbase + B_HI_OFF + (unsigned)(nh * 256 * ROWB) + boff;

    float loss_acc = 0.0f;
    const int nchunks = nrows / TILE_M;

    // ---- prefetch first tile into staging ----
    {
        const float4* src = (const float4*)inp + (size_t)blockIdx.x * (TILE_M * DIMV / 4);
#pragma unroll
        for (int i = 0; i < 4; i++)
            cp_async16(sbase + STAGE_OFF + (tid + i * TPB) * 16, src + tid + i * TPB);
        CP_COMMIT();
    }

    for (int tile = blockIdx.x; tile < nchunks; tile += gridDim.x) {
        CP_WAIT0();
        __syncthreads();   // S1: staging visible; prev refine/scatter done

        // ---- convert x -> fp16 hi/lo in smem (x kept in v regs) ----
        float4 v[4];
        const float4* stg = (const float4*)(sm + STAGE_OFF);
#pragma unroll
        for (int i = 0; i < 4; i++) {
            int idx = tid + i * TPB;
            float4 x = stg[idx];
            v[i] = x;
            __half h0 = __float2half_rn(x.x), h1 = __float2half_rn(x.y);
            __half h2 = __float2half_rn(x.z), h3 = __float2half_rn(x.w);
            __half l0 = __float2half_rn(x.x - __half2float(h0));
            __half l1 = __float2half_rn(x.y - __half2float(h1));
            __half l2 = __float2half_rn(x.z - __half2float(h2));
            __half l3 = __float2half_rn(x.w - __half2float(h3));
            unsigned hw0 = __half_as_ushort(h0) | ((unsigned)__half_as_ushort(h1) << 16);
            unsigned hw1 = __half_as_ushort(h2) | ((unsigned)__half_as_ushort(h3) << 16);
            unsigned lw0 = __half_as_ushort(l0) | ((unsigned)__half_as_ushort(l1) << 16);
            unsigned lw1 = __half_as_ushort(l2) | ((unsigned)__half_as_ushort(l3) << 16);
            unsigned long long hw = ((unsigned long long)hw1 << 32) | hw0;
            unsigned long long lw = ((unsigned long long)lw1 << 32) | lw0;
            int row = idx >> 4, kc = idx & 15;
            *(unsigned long long*)(sm + A_HI_OFF + row * ROWB + kc * 8) = hw;
            *(unsigned long long*)(sm + A_LO_OFF + row * ROWB + kc * 8) = lw;
        }
        __syncthreads();   // S2: A smem ready; staging reads done

        // ---- prefetch next tile (overlaps MMA) ----
        {
            int nxt = tile + gridDim.x;
            if (nxt < nchunks) {
                const float4* src = (const float4*)inp + (size_t)nxt * (TILE_M * DIMV / 4);
#pragma unroll
                for (int i = 0; i < 4; i++)
                    cp_async16(sbase + STAGE_OFF + (tid + i * TPB) * 16, src + tid + i * TPB);
            }
            CP_COMMIT();
        }

        // ---- load A hi fragments ----
        unsigned Ah[4][4];
#pragma unroll
        for (int ks = 0; ks < 4; ks++)
            ldm_x4(Ah[ks][0], Ah[ks][1], Ah[ks][2], Ah[ks][3], aHbase + (unsigned)(ks * 32));

        // ---- single-pass screen GEMM; 8-bit-index positive-key top-2 ----
        unsigned bk1[2] = {0xFFFFFFFFu, 0xFFFFFFFFu};
        unsigned bk2[2] = {0xFFFFFFFFu, 0xFFFFFFFFu};

#pragma unroll
        for (int chunk = 0; chunk < 4; chunk++) {
            float acc[8][4];
            int jb0 = chunk * 64 + (lane & 3) * 2;      // local index within half
#pragma unroll
            for (int nt = 0; nt < 8; nt++) {
                float2 wq = *(float2*)(swsqp + nh * 256 + jb0 + nt * 8);
                acc[nt][0] = wq.x; acc[nt][1] = wq.y;
                acc[nt][2] = wq.x; acc[nt][3] = wq.y;
            }
            unsigned bc = (unsigned)(chunk * 64 * ROWB);
#pragma unroll
            for (int ks = 0; ks < 4; ks++) {
                unsigned B0[4][4];
#pragma unroll
                for (int pr = 0; pr < 4; pr++) {
                    unsigned off = bc + (unsigned)(pr * 16 * ROWB + ks * 32);
                    ldm_x4(B0[pr][0], B0[pr][1], B0[pr][2], B0[pr][3], bHbase + off);
                }
#pragma unroll
                for (int pr = 0; pr < 4; pr++) {
                    mma_fp16(acc[2*pr],   Ah[ks], B0[pr][0], B0[pr][1]);
                    mma_fp16(acc[2*pr+1], Ah[ks], B0[pr][2], B0[pr][3]);
                }
            }
            // fold: values = d + POS_OFF > 0; key = (bits & ~0xFF) | j8
#pragma unroll
            for (int nt = 0; nt < 8; nt++) {
                int jb = jb0 + nt * 8;
#pragma unroll
                for (int q = 0; q < 4; q++) {
                    int s = q >> 1;
                    unsigned key = (__float_as_uint(acc[nt][q]) & ~0xFFu) | (unsigned)(jb + (q & 1));
                    unsigned t = umx(bk1[s], key);
                    bk1[s] = umn(bk1[s], key);
                    bk2[s] = umn(bk2[s], t);
                }
            }
        }

        // ---- quad-merge u32 top-2, owners write per-half keys ----
#pragma unroll
        for (int s = 0; s < 2; s++) {
            unsigned k1 = bk1[s], k2 = bk2[s];
#pragma unroll
            for (int off = 1; off <= 2; off <<= 1) {
                unsigned o1 = __shfl_xor_sync(0xFFFFFFFFu, k1, off);
                unsigned o2 = __shfl_xor_sync(0xFFFFFFFFu, k2, off);
                unsigned t = umx(k1, o1);
                k1 = umn(k1, o1);
                k2 = umn(k2, umn(o2, t));
            }
            if ((lane & 3) == 0) {
                int r = mgrp * 16 + (lane >> 2) + s * 8;
                skey[(nh * 128 + r) * 2]     = k1;
                skey[(nh * 128 + r) * 2 + 1] = k2;
            }
        }
        __syncthreads();   // S3: both halves' top-2 keys in smem

        // ---- exact refine: expand half-keys to 9-bit j, merge, recompute ----
        if (tid < 2 * TILE_M) {
            int r = tid >> 1;
            unsigned long long ea1 = kexp(skey[r * 2], 0);
            unsigned long long ea2 = kexp(skey[r * 2 + 1], 0);
            unsigned long long eb1 = kexp(skey[(128 + r) * 2], 1);
            unsigned long long eb2 = kexp(skey[(128 + r) * 2 + 1], 1);
            unsigned long long m1 = u64min(ea1, eb1);
            unsigned long long m2 = u64min(u64max(ea1, eb1), u64min(ea2, eb2));
            int j = (int)(((tid & 1) ? m2 : m1) & 0x1FFull);

            const uint4* xh4 = (const uint4*)(sm + A_HI_OFF + r * ROWB);
            const uint4* xl4 = (const uint4*)(sm + A_LO_OFF + r * ROWB);
            const uint4* wh4 = (const uint4*)(sm + B_HI_OFF + j * ROWB);
            const uint4* wl4 = (const uint4*)(sm + B_LO_OFF + j * ROWB);
            float d  = swsq[j], d2 = 0.0f;
            float e  = 0.0f,    e2 = 0.0f;        // ||x||^2 split chains
#pragma unroll
            for (int c = 0; c < 8; c++) {
                uint4 hx = xh4[c], lx = xl4[c], hw = wh4[c], lw = wl4[c];
                const unsigned hxs[4] = {hx.x, hx.y, hx.z, hx.w};
                const unsigned lxs[4] = {lx.x, lx.y, lx.z, lx.w};
                const unsigned hws[4] = {hw.x, hw.y, hw.z, hw.w};
                const unsigned lws[4] = {lw.x, lw.y, lw.z, lw.w};
#pragma unroll
                for (int u = 0; u < 4; u++) {
                    float2 xa = h2f2(hxs[u]), xb = h2f2(lxs[u]);
                    float2 wa = h2f2(hws[u]), wb = h2f2(lws[u]);
                    float xx0 = xa.x + xb.x, xx1 = xa.y + xb.y;
                    float ww0 = wa.x + wb.x, ww1 = wa.y + wb.y;
                    d  = fmaf(xx0, ww0, d);
                    d2 = fmaf(xx1, ww1, d2);
                    e  = fmaf(xx0, xx0, e);
                    e2 = fmaf(xx1, xx1, e2);
                }
            }
            d += d2;
            e += e2;
            unsigned long long kd = packkey(d, j);
            unsigned long long ko = __shfl_xor_sync(0xFFFFFFFFu, kd, 1);
            if ((tid & 1) == 0) {
                unsigned long long kw = u64min(kd, ko);
                int jw = (int)(kw & 0xFFFFFFFFull);
                float dw;
                { unsigned m = (unsigned)(kw >> 32);
                  unsigned uu = (m & 0x80000000u) ? (m ^ 0x80000000u) : ~m;
                  dw = __uint_as_float(uu); }
                sj[r] = jw;
                loss_acc += dw + e;
                atomicAdd(&scnt[jw], 1.0f);
            }
        }
        __syncthreads();   // S4: sj ready

        // ---- embed_sum scatter straight from fp32 registers ----
#pragma unroll
        for (int i = 0; i < 4; i++) {
            int idx = tid + i * TPB;
            int r = idx >> 4;
            int j = sj[r];
            red_add_v4(g_embed_sum + j * DIMV + (idx & 15) * 4, v[i].x, v[i].y, v[i].z, v[i].w);
        }
    }

    // ---- flush block-local accumulators ----
    atomicAdd(sloss, loss_acc);
    __syncthreads();
    if (scnt[tid] != 0.0f) atomicAdd(&g_counts[tid], scnt[tid]);
    if (tid == 0) atomicAdd(&g_loss_sum, *sloss);
}

// ---------------------------------------------------------------------------
// Kernel 3 (fused tail): every block redundantly reduces n, computes its 256
// outputs; block 0 additionally writes loss/perplexity/new_cluster_size.
// ---------------------------------------------------------------------------
__global__ void vq_final(const float* __restrict__ cs_in,
                         const float* __restrict__ ea_in,
                         float* __restrict__ out, int nrows) {
    __shared__ float red[256];
    const int t = threadIdx.x;
    const int b = blockIdx.x;

    float c0 = g_counts[t], c1 = g_counts[t + 256];
    float ncs0 = fmaf(0.99f, cs_in[t], 0.01f * c0);
    float ncs1 = fmaf(0.99f, cs_in[t + 256], 0.01f * c1);

    red[t] = ncs0 + ncs1;
    __syncthreads();
#pragma unroll
    for (int off = 128; off; off >>= 1) {
        if (t < off) red[t] += red[t + off];
        __syncthreads();
    }
    float n = red[0];

    int gid = b * 256 + t;
    int k = gid >> 9;
    int j = (b & 1) * 256 + t;
    float ncs = (b & 1) ? ncs1 : ncs0;
    float csj = (ncs + 1e-5f) / (n + (float)NEMB * 1e-5f) * n;

    float ea = fmaf(0.99f, ea_in[gid], 0.01f * g_embed_sum[j * DIMV + k]);
    const int EA_OFF = 2 + DIMV * NEMB + NEMB;
    out[EA_OFF + gid] = ea;              // new_embed_avg
    out[2 + gid] = ea / csj;             // new_w

    if (b == 0) {
        out[2 + DIMV * NEMB + t]       = ncs0;   // new_cluster_size
        out[2 + DIMV * NEMB + t + 256] = ncs1;
        __syncthreads();
        float p0 = c0 / (float)nrows, p1 = c1 / (float)nrows;
        red[t] = fmaf(p0, logf(p0 + 1e-10f), p1 * logf(p1 + 1e-10f));
        __syncthreads();
#pragma unroll
        for (int off = 128; off; off >>= 1) {
            if (t < off) red[t] += red[t + off];
            __syncthreads();
        }
        if (t == 0) {
            out[1] = expf(-red[0]);
            out[0] = 0.25f * g_loss_sum / ((float)nrows * (float)DIMV);
        }
    }
}

// ---------------------------------------------------------------------------
extern "C" void kernel_launch(void* const* d_in, const int* in_sizes, int n_in,
                              void* d_out, int out_size) {
    const float* inp = (const float*)d_in[0];
    const float* w   = (const float*)d_in[1];
    const float* cs  = (const float*)d_in[2];
    const float* ea  = (const float*)d_in[3];
    int nrows = in_sizes[0] / DIMV;

    cudaFuncSetAttribute(vq_main, cudaFuncAttributeMaxDynamicSharedMemorySize, SMEM_BYTES);

    vq_init<<<80, 256>>>(w);
    vq_main<<<148, TPB, SMEM_BYTES>>>(inp, nrows);
    vq_final<<<DIMV * NEMB / 256, 256>>>(cs, ea, (float*)d_out, nrows);
}